// round 8
// baseline (speedup 1.0000x reference)
#include <cuda_runtime.h>
#include <cuda_fp16.h>
#include <cstdint>

// y = conv2d(x[1,512,512,16], w[3,3,16,64], SAME); pot = y + old
// spike = pot >= 1; new_pot = spike ? 0 : pot
// d_out: [spikes 512*512*64][new_pot 512*512*64]
//
// HMMA implicit GEMM (mma.sync m16n8k16 f16, f32 acc), split-2 fp16 emulation.
// Block tile: 256 x-pixels (one y row) x 64 couts; warp: 32 px x 64 couts.
// Warp-M=32 halves B-fragment smem traffic per output (R7 was L1-bound on B).

#define HH 512
#define WW 512
#define CIN 16
#define COUT 64

#define B_BYTES (9 * 2 * 8 * 32 * 8)   /* 36864 */
#define A_PITCH 48                     /* bytes per pixel-row */
#define A_BUF   (258 * A_PITCH)        /* 12384 per (split,row) buffer */
#define A_OFF   B_BYTES
#define SMEM_TOTAL (A_OFF + 6 * A_BUF) /* 36864 + 74304 = 111168; x2 = 222336 */

__device__ static uint2 g_Bfrag[9 * 2 * 8 * 32];

__device__ __forceinline__ uint32_t smem_u32(const void* p) {
    uint32_t a;
    asm("{ .reg .u64 t; cvta.to.shared.u64 t, %1; cvt.u32.u64 %0, t; }"
        : "=r"(a) : "l"(p));
    return a;
}
__device__ __forceinline__ uint32_t pack_h2(float a, float b) {
    __half2 h = __floats2half2_rn(a, b);
    return *(uint32_t*)&h;
}
__device__ __forceinline__ float h_rt(float v) {
    return __half2float(__float2half_rn(v));
}
__device__ __forceinline__ void ldmatrix_x4(uint32_t* r, uint32_t addr) {
    asm volatile("ldmatrix.sync.aligned.m8n8.x4.shared.b16 {%0,%1,%2,%3}, [%4];"
                 : "=r"(r[0]), "=r"(r[1]), "=r"(r[2]), "=r"(r[3]) : "r"(addr));
}
__device__ __forceinline__ void mma_f16(float* d, const uint32_t* a, uint2 b) {
    asm volatile(
        "mma.sync.aligned.m16n8k16.row.col.f32.f16.f16.f32 "
        "{%0,%1,%2,%3}, {%4,%5,%6,%7}, {%8,%9}, {%0,%1,%2,%3};"
        : "+f"(d[0]), "+f"(d[1]), "+f"(d[2]), "+f"(d[3])
        : "r"(a[0]), "r"(a[1]), "r"(a[2]), "r"(a[3]), "r"(b.x), "r"(b.y));
}

// ---- prep: build B fragments (hi/lo) in m16n8k16 .col lane layout ----
__global__ void prep_weights(const float* __restrict__ wt) {
    int idx = blockIdx.x * 256 + threadIdx.x;
    if (idx >= 9 * 2 * 8 * 32) return;
    int lane = idx & 31;
    int t = idx >> 5;
    int nt = t & 7;  t >>= 3;
    int s = t & 1;
    int tap = t >> 1;
    int g = lane >> 2, tg = lane & 3;
    int n = nt * 8 + g;
    float w[4];
    int kk[4] = {tg * 2, tg * 2 + 1, tg * 2 + 8, tg * 2 + 9};
    #pragma unroll
    for (int j = 0; j < 4; j++) {
        float wv = wt[(tap * 16 + kk[j]) * 64 + n];
        w[j] = s == 0 ? wv : (wv - h_rt(wv));
    }
    g_Bfrag[idx] = make_uint2(pack_h2(w[0], w[1]), pack_h2(w[2], w[3]));
}

// ---- main kernel ----
__global__ void __launch_bounds__(256, 2)
snn_conv_mma(const float* __restrict__ in, const float* __restrict__ oldp,
             float* __restrict__ out_spk, float* __restrict__ out_pot) {
    extern __shared__ char smem[];
    const uint32_t sb = smem_u32(smem);
    const int tid = threadIdx.x;
    const int wid = tid >> 5;
    const int lane = tid & 31;
    const int x0 = blockIdx.x * 256;
    const int y  = blockIdx.y;

    // ---- stage B fragments (straight copy) ----
    {
        const uint4* src = (const uint4*)g_Bfrag;
        uint4* dst = (uint4*)smem;
        #pragma unroll
        for (int i = tid; i < B_BYTES / 16; i += 256) dst[i] = src[i];
    }
    // ---- stage A: 3 source rows x 258 px x 16 ci, split hi/lo fp16 ----
    for (int i = tid; i < 3 * 258 * 4; i += 256) {
        int q = i & 3;
        int t = i >> 2;
        int p = t % 258;          // buffer row (gx = x0 + p - 1)
        int r = t / 258;          // source row (gy = y + r - 1)
        int gx = x0 + p - 1, gy = y + r - 1;
        float4 v = make_float4(0.f, 0.f, 0.f, 0.f);
        if ((unsigned)gx < WW && (unsigned)gy < HH)
            v = *(const float4*)(in + (gy * WW + gx) * CIN + q * 4);
        float hx = h_rt(v.x), hy = h_rt(v.y);
        float hz = h_rt(v.z), hw = h_rt(v.w);
        char* rh = smem + A_OFF + r * A_BUF + p * A_PITCH + q * 8;
        char* rl = rh + 3 * A_BUF;
        *(uint32_t*)(rh)     = pack_h2(v.x, v.y);
        *(uint32_t*)(rh + 4) = pack_h2(v.z, v.w);
        *(uint32_t*)(rl)     = pack_h2(v.x - hx, v.y - hy);
        *(uint32_t*)(rl + 4) = pack_h2(v.z - hz, v.w - hw);
    }
    __syncthreads();

    // warp tile: pixels m0..m0+31, all 64 couts
    const int m0 = wid * 32;
    const uint32_t rowsel = (lane & 7) + ((lane >> 3) & 1) * 8;
    const uint32_t koff = (lane >> 4) * 16;

    float acc[2][8][4];
    #pragma unroll
    for (int t = 0; t < 2; t++)
        #pragma unroll
        for (int nt = 0; nt < 8; nt++)
            #pragma unroll
            for (int j = 0; j < 4; j++) acc[t][nt][j] = 0.f;

    #pragma unroll
    for (int tap = 0; tap < 9; tap++) {
        const int dy = tap / 3, dx = tap - dy * 3;
        // B loads first (shared across both 16-px halves)
        const char* bb = smem + (tap * 2 * 8 * 32 + lane) * 8;
        uint2 bh[8], bl[8];
        #pragma unroll
        for (int nt = 0; nt < 8; nt++) {
            bh[nt] = *(const uint2*)(bb + nt * 256);
            bl[nt] = *(const uint2*)(bb + nt * 256 + 2048);
        }
        uint32_t abase = sb + A_OFF + dy * A_BUF +
                         (m0 + dx + rowsel) * A_PITCH + koff;
        #pragma unroll
        for (int t = 0; t < 2; t++) {
            uint32_t ah[4], al[4];
            uint32_t aaddr = abase + t * (16 * A_PITCH);
            ldmatrix_x4(ah, aaddr);
            ldmatrix_x4(al, aaddr + 3 * A_BUF);
            #pragma unroll
            for (int nt = 0; nt < 8; nt++) {
                mma_f16(acc[t][nt], ah, bh[nt]);   // hi * hi
                mma_f16(acc[t][nt], ah, bl[nt]);   // hi * lo_w
                mma_f16(acc[t][nt], al, bh[nt]);   // lo_x * hi
            }
        }
    }

    // ---- epilogue: +old, threshold, reset, store both outputs ----
    const int g = lane >> 2, tg = lane & 3;
    #pragma unroll
    for (int t = 0; t < 2; t++) {
        #pragma unroll
        for (int half = 0; half < 2; half++) {
            int m = m0 + t * 16 + half * 8 + g;
            int base = (y * WW + x0 + m) * COUT + tg * 2;
            #pragma unroll
            for (int nt = 0; nt < 8; nt++) {
                int off = base + nt * 8;
                float2 o = *(const float2*)(oldp + off);
                float v0 = acc[t][nt][half * 2 + 0] + o.x;
                float v1 = acc[t][nt][half * 2 + 1] + o.y;
                bool f0 = v0 >= 1.f, f1 = v1 >= 1.f;
                *(float2*)(out_spk + off) =
                    make_float2(f0 ? 1.f : 0.f, f1 ? 1.f : 0.f);
                *(float2*)(out_pot + off) =
                    make_float2(f0 ? 0.f : v0, f1 ? 0.f : v1);
            }
        }
    }
}

extern "C" void kernel_launch(void* const* d_in, const int* in_sizes, int n_in,
                              void* d_out, int out_size) {
    const float* in   = (const float*)d_in[0];   // [1,512,512,16]
    const float* wt   = (const float*)d_in[1];   // [3,3,16,64]
    const float* oldp = (const float*)d_in[2];   // [1,512,512,64]
    float* spk = (float*)d_out;
    float* pot = (float*)d_out + in_sizes[2];

    prep_weights<<<(9 * 2 * 8 * 32 + 255) / 256, 256>>>(wt);

    cudaFuncSetAttribute(snn_conv_mma,
                         cudaFuncAttributeMaxDynamicSharedMemorySize, SMEM_TOTAL);
    dim3 grid(WW / 256, HH);   // 2 x 512
    snn_conv_mma<<<grid, 256, SMEM_TOTAL>>>(in, oldp, spk, pot);
}

// round 9
// speedup vs baseline: 1.1966x; 1.1966x over previous
#include <cuda_runtime.h>
#include <cuda_fp16.h>
#include <cstdint>

// y = conv2d(x[1,512,512,16], w[3,3,16,64], SAME); pot = y + old
// spike = pot >= 1; new_pot = spike ? 0 : pot
// d_out: [spikes 512*512*64][new_pot 512*512*64]
//
// HMMA implicit GEMM (mma.sync m16n8k16 f16, f32 acc), split-2 fp16 emulation.
// Warp tile 32 px x 32 couts (balanced -> min smem traffic at fixed acc regs);
// block = 128 px x 64 couts; 3 CTAs/SM.

#define HH 512
#define WW 512
#define CIN 16
#define COUT 64

#define B_BYTES (9 * 2 * 8 * 32 * 8)   /* 36864 */
#define A_PITCH 48                     /* bytes per pixel-row: 16 ci f16 + pad */
#define A_BUF   (130 * A_PITCH)        /* 6240 per (split,row) buffer */
#define A_OFF   B_BYTES
#define SMEM_TOTAL (A_OFF + 6 * A_BUF) /* 74304 ; x3 CTAs = 222912 <= 228KB */

__device__ static uint2 g_Bfrag[9 * 2 * 8 * 32];

__device__ __forceinline__ uint32_t smem_u32(const void* p) {
    uint32_t a;
    asm("{ .reg .u64 t; cvta.to.shared.u64 t, %1; cvt.u32.u64 %0, t; }"
        : "=r"(a) : "l"(p));
    return a;
}
__device__ __forceinline__ uint32_t pack_h2(float a, float b) {
    __half2 h = __floats2half2_rn(a, b);
    return *(uint32_t*)&h;
}
__device__ __forceinline__ float h_rt(float v) {
    return __half2float(__float2half_rn(v));
}
__device__ __forceinline__ void ldmatrix_x4(uint32_t* r, uint32_t addr) {
    asm volatile("ldmatrix.sync.aligned.m8n8.x4.shared.b16 {%0,%1,%2,%3}, [%4];"
                 : "=r"(r[0]), "=r"(r[1]), "=r"(r[2]), "=r"(r[3]) : "r"(addr));
}
__device__ __forceinline__ void mma_f16(float* d, const uint32_t* a, uint2 b) {
    asm volatile(
        "mma.sync.aligned.m16n8k16.row.col.f32.f16.f16.f32 "
        "{%0,%1,%2,%3}, {%4,%5,%6,%7}, {%8,%9}, {%0,%1,%2,%3};"
        : "+f"(d[0]), "+f"(d[1]), "+f"(d[2]), "+f"(d[3])
        : "r"(a[0]), "r"(a[1]), "r"(a[2]), "r"(a[3]), "r"(b.x), "r"(b.y));
}

// ---- prep: build B fragments (hi/lo) in m16n8k16 .col lane layout ----
__global__ void prep_weights(const float* __restrict__ wt) {
    int idx = blockIdx.x * 256 + threadIdx.x;
    if (idx >= 9 * 2 * 8 * 32) return;
    int lane = idx & 31;
    int t = idx >> 5;
    int nt = t & 7;  t >>= 3;
    int s = t & 1;
    int tap = t >> 1;
    int g = lane >> 2, tg = lane & 3;
    int n = nt * 8 + g;
    float w[4];
    int kk[4] = {tg * 2, tg * 2 + 1, tg * 2 + 8, tg * 2 + 9};
    #pragma unroll
    for (int j = 0; j < 4; j++) {
        float wv = wt[(tap * 16 + kk[j]) * 64 + n];
        w[j] = s == 0 ? wv : (wv - h_rt(wv));
    }
    g_Bfrag[idx] = make_uint2(pack_h2(w[0], w[1]), pack_h2(w[2], w[3]));
}

// ---- main kernel ----
__global__ void __launch_bounds__(256, 3)
snn_conv_mma(const float* __restrict__ in, const float* __restrict__ oldp,
             float* __restrict__ out_spk, float* __restrict__ out_pot) {
    extern __shared__ char smem[];
    const uint32_t sb = smem_u32(smem);
    const int tid = threadIdx.x;
    const int wid = tid >> 5;
    const int lane = tid & 31;
    const int x0 = blockIdx.x * 128;
    const int y  = blockIdx.y;

    // ---- stage B fragments (straight copy) ----
    {
        const uint4* src = (const uint4*)g_Bfrag;
        uint4* dst = (uint4*)smem;
        #pragma unroll
        for (int i = tid; i < B_BYTES / 16; i += 256) dst[i] = src[i];
    }
    // ---- stage A: 3 source rows x 130 px x 16 ci, split hi/lo fp16 ----
    for (int i = tid; i < 3 * 130 * 4; i += 256) {
        int q = i & 3;
        int t = i >> 2;
        int p = t % 130;          // buffer row (gx = x0 + p - 1)
        int r = t / 130;          // source row (gy = y + r - 1)
        int gx = x0 + p - 1, gy = y + r - 1;
        float4 v = make_float4(0.f, 0.f, 0.f, 0.f);
        if ((unsigned)gx < WW && (unsigned)gy < HH)
            v = *(const float4*)(in + (gy * WW + gx) * CIN + q * 4);
        float hx = h_rt(v.x), hy = h_rt(v.y);
        float hz = h_rt(v.z), hw = h_rt(v.w);
        char* rh = smem + A_OFF + r * A_BUF + p * A_PITCH + q * 8;
        char* rl = rh + 3 * A_BUF;
        *(uint32_t*)(rh)     = pack_h2(v.x, v.y);
        *(uint32_t*)(rh + 4) = pack_h2(v.z, v.w);
        *(uint32_t*)(rl)     = pack_h2(v.x - hx, v.y - hy);
        *(uint32_t*)(rl + 4) = pack_h2(v.z - hz, v.w - hw);
    }
    __syncthreads();

    // warp tile: pixels m0..m0+31, couts cb..cb+31
    const int m0 = (wid >> 1) * 32;
    const int cb = (wid & 1) * 32;
    const uint32_t rowsel = (lane & 7) + ((lane >> 3) & 1) * 8;
    const uint32_t koff = (lane >> 4) * 16;

    float acc[2][4][4];    // [px-half][n-tile][frag]
    #pragma unroll
    for (int t = 0; t < 2; t++)
        #pragma unroll
        for (int nt = 0; nt < 4; nt++)
            #pragma unroll
            for (int j = 0; j < 4; j++) acc[t][nt][j] = 0.f;

    #pragma unroll
    for (int tap = 0; tap < 9; tap++) {
        const int dy = tap / 3, dx = tap - dy * 3;
        // B loads first (4 n-tiles for this warp's cout half)
        const char* bb = smem + (tap * 2 * 8 * 32 + lane) * 8 + (cb / 8) * 256;
        uint2 bh[4], bl[4];
        #pragma unroll
        for (int nt = 0; nt < 4; nt++) {
            bh[nt] = *(const uint2*)(bb + nt * 256);
            bl[nt] = *(const uint2*)(bb + nt * 256 + 2048);
        }
        uint32_t abase = sb + A_OFF + dy * A_BUF +
                         (m0 + dx + rowsel) * A_PITCH + koff;
        #pragma unroll
        for (int t = 0; t < 2; t++) {
            uint32_t ah[4], al[4];
            uint32_t aaddr = abase + t * (16 * A_PITCH);
            ldmatrix_x4(ah, aaddr);
            ldmatrix_x4(al, aaddr + 3 * A_BUF);
            #pragma unroll
            for (int nt = 0; nt < 4; nt++) {
                mma_f16(acc[t][nt], ah, bh[nt]);   // hi * hi
                mma_f16(acc[t][nt], ah, bl[nt]);   // hi * lo_w
                mma_f16(acc[t][nt], al, bh[nt]);   // lo_x * hi
            }
        }
    }

    // ---- epilogue: +old, threshold, reset, store both outputs ----
    const int g = lane >> 2, tg = lane & 3;
    #pragma unroll
    for (int t = 0; t < 2; t++) {
        #pragma unroll
        for (int half = 0; half < 2; half++) {
            int m = m0 + t * 16 + half * 8 + g;
            int base = (y * WW + x0 + m) * COUT + cb + tg * 2;
            #pragma unroll
            for (int nt = 0; nt < 4; nt++) {
                int off = base + nt * 8;
                float2 o = *(const float2*)(oldp + off);
                float v0 = acc[t][nt][half * 2 + 0] + o.x;
                float v1 = acc[t][nt][half * 2 + 1] + o.y;
                bool f0 = v0 >= 1.f, f1 = v1 >= 1.f;
                *(float2*)(out_spk + off) =
                    make_float2(f0 ? 1.f : 0.f, f1 ? 1.f : 0.f);
                *(float2*)(out_pot + off) =
                    make_float2(f0 ? 0.f : v0, f1 ? 0.f : v1);
            }
        }
    }
}

extern "C" void kernel_launch(void* const* d_in, const int* in_sizes, int n_in,
                              void* d_out, int out_size) {
    const float* in   = (const float*)d_in[0];   // [1,512,512,16]
    const float* wt   = (const float*)d_in[1];   // [3,3,16,64]
    const float* oldp = (const float*)d_in[2];   // [1,512,512,64]
    float* spk = (float*)d_out;
    float* pot = (float*)d_out + in_sizes[2];

    prep_weights<<<(9 * 2 * 8 * 32 + 255) / 256, 256>>>(wt);

    cudaFuncSetAttribute(snn_conv_mma,
                         cudaFuncAttributeMaxDynamicSharedMemorySize, SMEM_TOTAL);
    dim3 grid(WW / 128, HH);   // 4 x 512
    snn_conv_mma<<<grid, 256, SMEM_TOTAL>>>(in, oldp, spk, pot);
}

// round 10
// speedup vs baseline: 1.2729x; 1.0638x over previous
#include <cuda_runtime.h>
#include <cuda_fp16.h>
#include <cstdint>

// y = conv2d(x[1,512,512,16], w[3,3,16,64], SAME); pot = y + old
// spike = pot >= 1; new_pot = spike ? 0 : pot
// d_out: [spikes 512*512*64][new_pot 512*512*64]
//
// HMMA implicit GEMM (mma.sync m16n8k16 f16, f32 acc), split-2 fp16 emulation.
// Warp tile 32 px x 32 couts; block = 128 px x 64 couts; 3 CTAs/SM.
// R10: MMA issue order made independence-first; cp.async B copy; .cs epilogue.

#define HH 512
#define WW 512
#define CIN 16
#define COUT 64

#define B_BYTES (9 * 2 * 8 * 32 * 8)   /* 36864 */
#define A_PITCH 48                     /* bytes per pixel-row: 16 ci f16 + pad */
#define A_BUF   (130 * A_PITCH)        /* 6240 per (split,row) buffer */
#define A_OFF   B_BYTES
#define SMEM_TOTAL (A_OFF + 6 * A_BUF) /* 74304 ; x3 CTAs = 222912 <= 228KB */

__device__ static uint2 g_Bfrag[9 * 2 * 8 * 32];

__device__ __forceinline__ uint32_t smem_u32(const void* p) {
    uint32_t a;
    asm("{ .reg .u64 t; cvta.to.shared.u64 t, %1; cvt.u32.u64 %0, t; }"
        : "=r"(a) : "l"(p));
    return a;
}
__device__ __forceinline__ uint32_t pack_h2(float a, float b) {
    __half2 h = __floats2half2_rn(a, b);
    return *(uint32_t*)&h;
}
__device__ __forceinline__ float h_rt(float v) {
    return __half2float(__float2half_rn(v));
}
__device__ __forceinline__ void ldmatrix_x4(uint32_t* r, uint32_t addr) {
    asm volatile("ldmatrix.sync.aligned.m8n8.x4.shared.b16 {%0,%1,%2,%3}, [%4];"
                 : "=r"(r[0]), "=r"(r[1]), "=r"(r[2]), "=r"(r[3]) : "r"(addr));
}
__device__ __forceinline__ void mma_f16(float* d, const uint32_t* a, uint2 b) {
    asm volatile(
        "mma.sync.aligned.m16n8k16.row.col.f32.f16.f16.f32 "
        "{%0,%1,%2,%3}, {%4,%5,%6,%7}, {%8,%9}, {%0,%1,%2,%3};"
        : "+f"(d[0]), "+f"(d[1]), "+f"(d[2]), "+f"(d[3])
        : "r"(a[0]), "r"(a[1]), "r"(a[2]), "r"(a[3]), "r"(b.x), "r"(b.y));
}
__device__ __forceinline__ void cp_async16(uint32_t dst, const void* src) {
    asm volatile("cp.async.cg.shared.global [%0], [%1], 16;"
                 :: "r"(dst), "l"(src) : "memory");
}

// ---- prep: build B fragments (hi/lo) in m16n8k16 .col lane layout ----
__global__ void prep_weights(const float* __restrict__ wt) {
    int idx = blockIdx.x * 256 + threadIdx.x;
    if (idx >= 9 * 2 * 8 * 32) return;
    int lane = idx & 31;
    int t = idx >> 5;
    int nt = t & 7;  t >>= 3;
    int s = t & 1;
    int tap = t >> 1;
    int g = lane >> 2, tg = lane & 3;
    int n = nt * 8 + g;
    float w[4];
    int kk[4] = {tg * 2, tg * 2 + 1, tg * 2 + 8, tg * 2 + 9};
    #pragma unroll
    for (int j = 0; j < 4; j++) {
        float wv = wt[(tap * 16 + kk[j]) * 64 + n];
        w[j] = s == 0 ? wv : (wv - h_rt(wv));
    }
    g_Bfrag[idx] = make_uint2(pack_h2(w[0], w[1]), pack_h2(w[2], w[3]));
}

// ---- main kernel ----
__global__ void __launch_bounds__(256, 3)
snn_conv_mma(const float* __restrict__ in, const float* __restrict__ oldp,
             float* __restrict__ out_spk, float* __restrict__ out_pot) {
    extern __shared__ char smem[];
    const uint32_t sb = smem_u32(smem);
    const int tid = threadIdx.x;
    const int wid = tid >> 5;
    const int lane = tid & 31;
    const int x0 = blockIdx.x * 128;
    const int y  = blockIdx.y;

    // ---- stage B fragments via cp.async (fire-and-forget until sync) ----
    #pragma unroll
    for (int i = tid; i < B_BYTES / 16; i += 256)
        cp_async16(sb + i * 16, (const char*)g_Bfrag + i * 16);
    asm volatile("cp.async.commit_group;" ::: "memory");

    // ---- stage A: 3 source rows x 130 px x 16 ci, split hi/lo fp16 ----
    for (int i = tid; i < 3 * 130 * 4; i += 256) {
        int q = i & 3;
        int t = i >> 2;
        int p = t % 130;          // buffer row (gx = x0 + p - 1)
        int r = t / 130;          // source row (gy = y + r - 1)
        int gx = x0 + p - 1, gy = y + r - 1;
        float4 v = make_float4(0.f, 0.f, 0.f, 0.f);
        if ((unsigned)gx < WW && (unsigned)gy < HH)
            v = *(const float4*)(in + (gy * WW + gx) * CIN + q * 4);
        float hx = h_rt(v.x), hy = h_rt(v.y);
        float hz = h_rt(v.z), hw = h_rt(v.w);
        char* rh = smem + A_OFF + r * A_BUF + p * A_PITCH + q * 8;
        char* rl = rh + 3 * A_BUF;
        *(uint32_t*)(rh)     = pack_h2(v.x, v.y);
        *(uint32_t*)(rh + 4) = pack_h2(v.z, v.w);
        *(uint32_t*)(rl)     = pack_h2(v.x - hx, v.y - hy);
        *(uint32_t*)(rl + 4) = pack_h2(v.z - hz, v.w - hw);
    }
    asm volatile("cp.async.wait_all;" ::: "memory");
    __syncthreads();

    // warp tile: pixels m0..m0+31, couts cb..cb+31
    const int m0 = (wid >> 1) * 32;
    const int cb = (wid & 1) * 32;
    const uint32_t rowsel = (lane & 7) + ((lane >> 3) & 1) * 8;
    const uint32_t koff = (lane >> 4) * 16;

    float acc[2][4][4];    // [px-half][n-tile][frag]
    #pragma unroll
    for (int t = 0; t < 2; t++)
        #pragma unroll
        for (int nt = 0; nt < 4; nt++)
            #pragma unroll
            for (int j = 0; j < 4; j++) acc[t][nt][j] = 0.f;

    #pragma unroll
    for (int tap = 0; tap < 9; tap++) {
        const int dy = tap / 3, dx = tap - dy * 3;
        // B loads first (4 n-tiles for this warp's cout half)
        const char* bb = smem + (tap * 2 * 8 * 32 + lane) * 8 + (cb / 8) * 256;
        uint2 bh[4], bl[4];
        #pragma unroll
        for (int nt = 0; nt < 4; nt++) {
            bh[nt] = *(const uint2*)(bb + nt * 256);
            bl[nt] = *(const uint2*)(bb + nt * 256 + 2048);
        }
        uint32_t abase = sb + A_OFF + dy * A_BUF +
                         (m0 + dx + rowsel) * A_PITCH + koff;
        #pragma unroll
        for (int t = 0; t < 2; t++) {
            uint32_t ah[4], al[4];
            uint32_t aaddr = abase + t * (16 * A_PITCH);
            ldmatrix_x4(ah, aaddr);
            ldmatrix_x4(al, aaddr + 3 * A_BUF);
            // independence-first issue order: 4-way parallel chains
            #pragma unroll
            for (int nt = 0; nt < 4; nt++) mma_f16(acc[t][nt], ah, bh[nt]);
            #pragma unroll
            for (int nt = 0; nt < 4; nt++) mma_f16(acc[t][nt], ah, bl[nt]);
            #pragma unroll
            for (int nt = 0; nt < 4; nt++) mma_f16(acc[t][nt], al, bh[nt]);
        }
    }

    // ---- epilogue: +old, threshold, reset, streaming stores ----
    const int g = lane >> 2, tg = lane & 3;
    #pragma unroll
    for (int t = 0; t < 2; t++) {
        #pragma unroll
        for (int half = 0; half < 2; half++) {
            int m = m0 + t * 16 + half * 8 + g;
            int base = (y * WW + x0 + m) * COUT + cb + tg * 2;
            #pragma unroll
            for (int nt = 0; nt < 4; nt++) {
                int off = base + nt * 8;
                float2 o = __ldcs((const float2*)(oldp + off));
                float v0 = acc[t][nt][half * 2 + 0] + o.x;
                float v1 = acc[t][nt][half * 2 + 1] + o.y;
                bool f0 = v0 >= 1.f, f1 = v1 >= 1.f;
                __stcs((float2*)(out_spk + off),
                       make_float2(f0 ? 1.f : 0.f, f1 ? 1.f : 0.f));
                __stcs((float2*)(out_pot + off),
                       make_float2(f0 ? 0.f : v0, f1 ? 0.f : v1));
            }
        }
    }
}

extern "C" void kernel_launch(void* const* d_in, const int* in_sizes, int n_in,
                              void* d_out, int out_size) {
    const float* in   = (const float*)d_in[0];   // [1,512,512,16]
    const float* wt   = (const float*)d_in[1];   // [3,3,16,64]
    const float* oldp = (const float*)d_in[2];   // [1,512,512,64]
    float* spk = (float*)d_out;
    float* pot = (float*)d_out + in_sizes[2];

    prep_weights<<<(9 * 2 * 8 * 32 + 255) / 256, 256>>>(wt);

    cudaFuncSetAttribute(snn_conv_mma,
                         cudaFuncAttributeMaxDynamicSharedMemorySize, SMEM_TOTAL);
    dim3 grid(WW / 128, HH);   // 4 x 512
    snn_conv_mma<<<grid, 256, SMEM_TOTAL>>>(in, oldp, spk, pot);
}